// round 8
// baseline (speedup 1.0000x reference)
#include <cuda_runtime.h>

// ---------------------------------------------------------------------------
// RandomProjectionQuantizer
//   h[t,:] = hidden[t,0:320] @ P[320,16]   (L2-normalize skipped: argmax is
//                                           invariant to positive row scale)
//   out[t] = (float)argmax_k <h[t], CB[k]> first-index ties; float32 output
//
// Argmax: DIM-packed f32x2 — (h[2e],h[2e+1]) is one u64 in natural layout,
// so both h and CB stream straight from memory with no packing. Dot = chain
// of 8 fma2 + horizontal add. Cross-chunk combine: atomicMax on sortable
// (score_bits, 0x7FFFFFFF - idx) keys (first-index tie-break preserved).
// ---------------------------------------------------------------------------

#define IN_DIM   320
#define E        16
#define CHUNK    256                 // codes per CTA chunk (16 KB smem)
#define THREADS  128
#define TPT      2                   // tokens per thread
#define TOKB     (THREADS * TPT)     // 256 tokens per CTA
#define TOKENS_MAX 16000

__device__ __align__(16) float              g_h[TOKENS_MAX * E];
__device__ __align__(16) unsigned long long g_keys[TOKENS_MAX];

typedef unsigned long long u64;

// ---- packed f32x2 ops -----------------------------------------------------
static __device__ __forceinline__ u64 mul2(u64 a, u64 b) {
    u64 d; asm("mul.rn.f32x2 %0, %1, %2;" : "=l"(d) : "l"(a), "l"(b)); return d;
}
static __device__ __forceinline__ u64 fma2(u64 a, u64 b, u64 c) {
    u64 d; asm("fma.rn.f32x2 %0, %1, %2, %3;" : "=l"(d) : "l"(a), "l"(b), "l"(c)); return d;
}
static __device__ __forceinline__ u64 add2(u64 a, u64 b) {
    u64 d; asm("add.rn.f32x2 %0, %1, %2;" : "=l"(d) : "l"(a), "l"(b)); return d;
}
static __device__ __forceinline__ void unpack2(float& lo, float& hi, u64 v) {
    asm("mov.b64 {%0, %1}, %2;" : "=f"(lo), "=f"(hi) : "l"(v));
}

// ---------------------------------------------------------------------------
// Projection (+ key init): one warp per token, P transposed in smem.
__global__ void rpq_proj(const float* __restrict__ hs,
                         const float* __restrict__ P, int ntok) {
    __shared__ float Pt[E * IN_DIM];
    int tid = threadIdx.x;
    for (int i = tid; i < IN_DIM * E; i += blockDim.x) {
        int d = i >> 4, e = i & 15;
        Pt[e * IN_DIM + d] = P[i];
    }
    __syncthreads();

    int warp = tid >> 5, lane = tid & 31;
    int t = blockIdx.x * 4 + warp;
    if (t >= ntok) return;

    if (lane == 0) g_keys[t] = 0ull;        // fused init

    const float* row = hs + (long long)t * IN_DIM;
    float acc[E];
#pragma unroll
    for (int e = 0; e < E; e++) acc[e] = 0.f;
#pragma unroll
    for (int j = 0; j < IN_DIM / 32; j++) {
        int d = lane + 32 * j;
        float x = row[d];
#pragma unroll
        for (int e = 0; e < E; e++)
            acc[e] = fmaf(x, Pt[e * IN_DIM + d], acc[e]);
    }
#pragma unroll
    for (int e = 0; e < E; e++) {
#pragma unroll
        for (int o = 16; o > 0; o >>= 1)
            acc[e] += __shfl_xor_sync(0xffffffffu, acc[e], o);
    }
    if (lane < E) g_h[t * E + lane] = acc[lane];
}

// ---------------------------------------------------------------------------
__global__ __launch_bounds__(THREADS)
void rpq_argmax(const float* __restrict__ CB, int ntok, int kcodes) {
    __shared__ __align__(16) float cb_s[CHUNK * E];   // 16 KB, natural layout

    const int tid   = threadIdx.x;
    const int kbase = blockIdx.y * CHUNK;

    // stage chunk: plain coalesced float4 copy (no packing needed)
    {
        const float4* src = (const float4*)(CB + (long long)kbase * E);
        float4* dst = (float4*)cb_s;
        for (int i = tid; i < CHUNK * E / 4; i += THREADS)
            dst[i] = src[i];
    }

    // load TPT tokens' h as packed dim-pairs (natural u64 layout)
    u64  hp[TPT][8];
    int  tok[TPT];
    bool valid[TPT];
#pragma unroll
    for (int i = 0; i < TPT; i++) {
        int t = blockIdx.x * TOKB + tid + i * THREADS;
        tok[i] = t;
        valid[i] = (t < ntok);
        const ulonglong2* hv =
            (const ulonglong2*)(g_h + (long long)(valid[i] ? t : 0) * E);
        ulonglong2 a = hv[0], b = hv[1], c = hv[2], d = hv[3];
        hp[i][0] = a.x; hp[i][1] = a.y; hp[i][2] = b.x; hp[i][3] = b.y;
        hp[i][4] = c.x; hp[i][5] = c.y; hp[i][6] = d.x; hp[i][7] = d.y;
    }
    __syncthreads();

    float best[TPT];
    int   bidx[TPT];
#pragma unroll
    for (int i = 0; i < TPT; i++) { best[i] = -3.402823466e38f; bidx[i] = 0; }

    const ulonglong2* cv = (const ulonglong2*)cb_s;
#pragma unroll 2
    for (int k = 0; k < CHUNK; ++k) {
        // one code = 16 floats = 4 x LDS.128, warp-broadcast
        ulonglong2 v0 = cv[k * 4 + 0];
        ulonglong2 v1 = cv[k * 4 + 1];
        ulonglong2 v2 = cv[k * 4 + 2];
        ulonglong2 v3 = cv[k * 4 + 3];
#pragma unroll
        for (int i = 0; i < TPT; i++) {
            u64 a0 = mul2(hp[i][0], v0.x);
            u64 a1 = mul2(hp[i][1], v0.y);
            a0 = fma2(hp[i][2], v1.x, a0);
            a1 = fma2(hp[i][3], v1.y, a1);
            a0 = fma2(hp[i][4], v2.x, a0);
            a1 = fma2(hp[i][5], v2.y, a1);
            a0 = fma2(hp[i][6], v3.x, a0);
            a1 = fma2(hp[i][7], v3.y, a1);
            a0 = add2(a0, a1);
            float lo, hi;
            unpack2(lo, hi, a0);
            float s = lo + hi;
            if (s > best[i]) { best[i] = s; bidx[i] = k; }   // keep first
        }
    }

#pragma unroll
    for (int i = 0; i < TPT; i++) {
        if (!valid[i]) continue;
        int gidx = kbase + bidx[i];
        unsigned ub = __float_as_uint(best[i]);
        ub = (ub & 0x80000000u) ? ~ub : (ub | 0x80000000u);  // sortable fp32
        u64 key = ((u64)ub << 32) | (unsigned)(0x7FFFFFFF - gidx);
        atomicMax(&g_keys[tok[i]], key);
    }
}

// ---------------------------------------------------------------------------
__global__ void rpq_finalize(float* __restrict__ out, int ntok, int total) {
    int t = blockIdx.x * blockDim.x + threadIdx.x;
    if (t < ntok)
        out[t] = (float)(0x7FFFFFFF - (int)(g_keys[t] & 0xFFFFFFFFull));
    else if (t < total)
        out[t] = 0.f;
}

// ---------------------------------------------------------------------------
extern "C" void kernel_launch(void* const* d_in, const int* in_sizes, int n_in,
                              void* d_out, int out_size) {
    // Bind by element count: hidden (largest), P (smallest), CB (remaining).
    int ih = 0, ip = 0;
    for (int i = 1; i < n_in; i++) {
        if (in_sizes[i] > in_sizes[ih]) ih = i;
        if (in_sizes[i] < in_sizes[ip]) ip = i;
    }
    int ic = 0;
    for (int i = 0; i < n_in; i++)
        if (i != ih && i != ip) ic = i;

    const float* hs = (const float*)d_in[ih];
    const float* P  = (const float*)d_in[ip];
    const float* CB = (const float*)d_in[ic];
    float* out = (float*)d_out;            // float32 labels (R6-proven)

    int ntok   = in_sizes[ih] / IN_DIM;    // 16000
    int kcodes = in_sizes[ic] / E;         // 8192

    rpq_proj<<<(ntok + 3) / 4, 128>>>(hs, P, ntok);

    dim3 g2((ntok + TOKB - 1) / TOKB, kcodes / CHUNK);   // (63, 32)
    rpq_argmax<<<g2, THREADS>>>(CB, ntok, kcodes);

    rpq_finalize<<<(out_size + 255) / 256, 256>>>(out, ntok, out_size);
}

// round 9
// speedup vs baseline: 1.3976x; 1.3976x over previous
#include <cuda_runtime.h>

// ---------------------------------------------------------------------------
// RandomProjectionQuantizer
//   h[t,:] = hidden[t,0:320] @ P[320,16]   (L2-normalize skipped: argmax is
//                                           invariant to positive row scale)
//   out[t] = (float)argmax_k <h[t], CB[k]> first-index ties; float32 output
//
// proj:   token-per-thread, P staged as native (e,e+1) u64 pairs, broadcast
//         LDS + fma2 -> ~4x fewer smem instructions than warp-per-token.
// argmax: code-PAIR-packed f32x2 (R7 variant, measured near its fma floor):
//         cbp[e] = (CB[2p][e], CB[2p+1][e]), h duplicated into both halves;
//         packed accumulator ends as (score_2p, score_2p+1), no horizontal
//         reduce. Cross-chunk combine: atomicMax on sortable keys.
// ---------------------------------------------------------------------------

#define IN_DIM   320
#define E        16
#define CHUNK    512                 // codes per argmax CTA (y-dim)
#define NPAIR    (CHUNK / 2)         // 256 pairs, 32 KB packed smem
#define THREADS  128
#define TPT      2                   // tokens per thread (argmax)
#define TOKB     (THREADS * TPT)     // 256 tokens per argmax CTA
#define PTHREADS 128                 // proj threads (1 token each)
#define TOKENS_MAX 16000

__device__ __align__(16) float              g_h[TOKENS_MAX * E];
__device__ __align__(16) unsigned long long g_keys[TOKENS_MAX];

typedef unsigned long long u64;

// ---- packed f32x2 ops -----------------------------------------------------
static __device__ __forceinline__ u64 mul2(u64 a, u64 b) {
    u64 d; asm("mul.rn.f32x2 %0, %1, %2;" : "=l"(d) : "l"(a), "l"(b)); return d;
}
static __device__ __forceinline__ u64 fma2(u64 a, u64 b, u64 c) {
    u64 d; asm("fma.rn.f32x2 %0, %1, %2, %3;" : "=l"(d) : "l"(a), "l"(b), "l"(c)); return d;
}
static __device__ __forceinline__ u64 add2(u64 a, u64 b) {
    u64 d; asm("add.rn.f32x2 %0, %1, %2;" : "=l"(d) : "l"(a), "l"(b)); return d;
}
static __device__ __forceinline__ u64 pack2(float lo, float hi) {
    u64 d; asm("mov.b64 %0, {%1, %2};" : "=l"(d) : "f"(lo), "f"(hi)); return d;
}
static __device__ __forceinline__ void unpack2(float& lo, float& hi, u64 v) {
    asm("mov.b64 {%0, %1}, %2;" : "=f"(lo), "=f"(hi) : "l"(v));
}

// ---------------------------------------------------------------------------
// Projection (+ fused key init): one TOKEN per THREAD.
// P[d][e] pairs (e even) are contiguous -> stage P verbatim, read as
// broadcast ulonglong2 (all lanes same addr, 1 phase). Per dim d:
// 4 broadcast LDS.128 + 8 fma2. acc2[ep] = (h[2ep], h[2ep+1]).
__global__ __launch_bounds__(PTHREADS)
void rpq_proj(const float* __restrict__ hs,
              const float* __restrict__ P, int ntok) {
    __shared__ __align__(16) float Ps[IN_DIM * E];    // 20 KB, verbatim copy
    const int tid = threadIdx.x;

    {
        const float4* src = (const float4*)P;
        float4* dst = (float4*)Ps;
        for (int i = tid; i < IN_DIM * E / 4; i += PTHREADS)
            dst[i] = src[i];
    }
    __syncthreads();

    const int t = blockIdx.x * PTHREADS + tid;
    if (t >= ntok) return;
    g_keys[t] = 0ull;                                 // fused init

    const float4* row = (const float4*)(hs + (long long)t * IN_DIM);
    const ulonglong2* Pv = (const ulonglong2*)Ps;     // Pv[d*2+q]: e-pairs

    u64 acc2[8];
#pragma unroll
    for (int ep = 0; ep < 8; ep++) acc2[ep] = 0ull;

#pragma unroll 4
    for (int j = 0; j < IN_DIM / 4; ++j) {            // 80 x LDG.128
        float4 x4 = row[j];
        float xs[4] = {x4.x, x4.y, x4.z, x4.w};
#pragma unroll
        for (int i = 0; i < 4; ++i) {
            int d = 4 * j + i;
            u64 xx = pack2(xs[i], xs[i]);
            ulonglong2 p01 = Pv[d * 2 + 0];           // broadcast LDS.128
            ulonglong2 p23 = Pv[d * 2 + 1];
            acc2[0] = fma2(xx, p01.x, acc2[0]);
            acc2[1] = fma2(xx, p01.y, acc2[1]);
            acc2[2] = fma2(xx, p23.x, acc2[2]);
            acc2[3] = fma2(xx, p23.y, acc2[3]);
            ulonglong2 p45 = Pv[d * 2 + 0 + IN_DIM];  // dummy-free: recompute
            // NOTE: e-pairs 4..7 live at qwords 2,3 of the same row
            (void)p45;
        }
    }
    // The loop above only covered e-pairs 0..3 (8 of 16 outputs). Second
    // sweep for e-pairs 4..7 would double LDG; instead do both in one pass:
    // (rewritten below — kept single-pass for all 8 pairs)
    // -- unreachable marker --
    // (see rpq_proj_full)
    {
        // store handled in rpq_proj_full
    }
    // Store: acc2 holds pairs 0..3 only — this function is superseded.
    (void)acc2;
}

// Full single-pass projection: all 8 e-pairs per dim (4 broadcast LDS.128).
__global__ __launch_bounds__(PTHREADS)
void rpq_proj_full(const float* __restrict__ hs,
                   const float* __restrict__ P, int ntok) {
    __shared__ __align__(16) float Ps[IN_DIM * E];    // 20 KB
    const int tid = threadIdx.x;

    {
        const float4* src = (const float4*)P;
        float4* dst = (float4*)Ps;
        for (int i = tid; i < IN_DIM * E / 4; i += PTHREADS)
            dst[i] = src[i];
    }
    __syncthreads();

    const int t = blockIdx.x * PTHREADS + tid;
    if (t >= ntok) return;
    g_keys[t] = 0ull;                                 // fused init

    const float4* row = (const float4*)(hs + (long long)t * IN_DIM);
    const ulonglong2* Pv = (const ulonglong2*)Ps;     // 4 qwords per dim row

    u64 acc2[8];
#pragma unroll
    for (int ep = 0; ep < 8; ep++) acc2[ep] = 0ull;

#pragma unroll 2
    for (int j = 0; j < IN_DIM / 4; ++j) {            // 80 x LDG.128
        float4 x4 = row[j];
        float xs[4] = {x4.x, x4.y, x4.z, x4.w};
#pragma unroll
        for (int i = 0; i < 4; ++i) {
            int d = 4 * j + i;
            u64 xx = pack2(xs[i], xs[i]);
            ulonglong2 pA = Pv[d * 4 + 0];            // e-pairs 0,1
            ulonglong2 pB = Pv[d * 4 + 1];            // e-pairs 2,3
            ulonglong2 pC = Pv[d * 4 + 2];            // e-pairs 4,5
            ulonglong2 pD = Pv[d * 4 + 3];            // e-pairs 6,7
            acc2[0] = fma2(xx, pA.x, acc2[0]);
            acc2[1] = fma2(xx, pA.y, acc2[1]);
            acc2[2] = fma2(xx, pB.x, acc2[2]);
            acc2[3] = fma2(xx, pB.y, acc2[3]);
            acc2[4] = fma2(xx, pC.x, acc2[4]);
            acc2[5] = fma2(xx, pC.y, acc2[5]);
            acc2[6] = fma2(xx, pD.x, acc2[6]);
            acc2[7] = fma2(xx, pD.y, acc2[7]);
        }
    }

    // acc2[ep] = (h[2ep], h[2ep+1]) — exactly g_h's natural layout.
    ulonglong2* outv = (ulonglong2*)(g_h + (long long)t * E);
    outv[0] = make_ulonglong2(acc2[0], acc2[1]);
    outv[1] = make_ulonglong2(acc2[2], acc2[3]);
    outv[2] = make_ulonglong2(acc2[4], acc2[5]);
    outv[3] = make_ulonglong2(acc2[6], acc2[7]);
}

// ---------------------------------------------------------------------------
// Argmax (R7 pair-packed variant — measured near its fma-pipe floor).
__global__ __launch_bounds__(THREADS)
void rpq_argmax(const float* __restrict__ CB, int ntok, int kcodes) {
    __shared__ __align__(16) u64 cbp[NPAIR * E];     // 32 KB

    const int tid   = threadIdx.x;
    const int kbase = blockIdx.y * CHUNK;

    for (int i = tid; i < NPAIR * 4; i += THREADS) {
        int p = i >> 2, q = i & 3;
        const float4* c0 = (const float4*)(CB + (long long)(kbase + 2 * p) * E) + q;
        const float4* c1 = (const float4*)(CB + (long long)(kbase + 2 * p + 1) * E) + q;
        float4 a = *c0, b = *c1;
        u64* dst = &cbp[p * E + q * 4];
        dst[0] = pack2(a.x, b.x);
        dst[1] = pack2(a.y, b.y);
        dst[2] = pack2(a.z, b.z);
        dst[3] = pack2(a.w, b.w);
    }

    u64  hd[TPT][E];
    int  tok[TPT];
    bool valid[TPT];
#pragma unroll
    for (int i = 0; i < TPT; i++) {
        int t = blockIdx.x * TOKB + tid + i * THREADS;
        tok[i] = t;
        valid[i] = (t < ntok);
        const float4* hv = (const float4*)(g_h + (long long)(valid[i] ? t : 0) * E);
        float4 h0 = hv[0], h1 = hv[1], h2 = hv[2], h3 = hv[3];
        hd[i][0]  = pack2(h0.x, h0.x); hd[i][1]  = pack2(h0.y, h0.y);
        hd[i][2]  = pack2(h0.z, h0.z); hd[i][3]  = pack2(h0.w, h0.w);
        hd[i][4]  = pack2(h1.x, h1.x); hd[i][5]  = pack2(h1.y, h1.y);
        hd[i][6]  = pack2(h1.z, h1.z); hd[i][7]  = pack2(h1.w, h1.w);
        hd[i][8]  = pack2(h2.x, h2.x); hd[i][9]  = pack2(h2.y, h2.y);
        hd[i][10] = pack2(h2.z, h2.z); hd[i][11] = pack2(h2.w, h2.w);
        hd[i][12] = pack2(h3.x, h3.x); hd[i][13] = pack2(h3.y, h3.y);
        hd[i][14] = pack2(h3.z, h3.z); hd[i][15] = pack2(h3.w, h3.w);
    }
    __syncthreads();

    float best[TPT];
    int   bidx[TPT];
#pragma unroll
    for (int i = 0; i < TPT; i++) { best[i] = -3.402823466e38f; bidx[i] = 0; }

    const ulonglong2* pv = (const ulonglong2*)cbp;
    for (int p = 0; p < NPAIR; ++p) {
        ulonglong2 v0 = pv[p * 8 + 0], v1 = pv[p * 8 + 1];
        ulonglong2 v2 = pv[p * 8 + 2], v3 = pv[p * 8 + 3];
        ulonglong2 v4 = pv[p * 8 + 4], v5 = pv[p * 8 + 5];
        ulonglong2 v6 = pv[p * 8 + 6], v7 = pv[p * 8 + 7];
#pragma unroll
        for (int i = 0; i < TPT; i++) {
            u64 a0 = mul2(hd[i][0],  v0.x);
            u64 a1 = mul2(hd[i][1],  v0.y);
            a0 = fma2(hd[i][2],  v1.x, a0);
            a1 = fma2(hd[i][3],  v1.y, a1);
            a0 = fma2(hd[i][4],  v2.x, a0);
            a1 = fma2(hd[i][5],  v2.y, a1);
            a0 = fma2(hd[i][6],  v3.x, a0);
            a1 = fma2(hd[i][7],  v3.y, a1);
            a0 = fma2(hd[i][8],  v4.x, a0);
            a1 = fma2(hd[i][9],  v4.y, a1);
            a0 = fma2(hd[i][10], v5.x, a0);
            a1 = fma2(hd[i][11], v5.y, a1);
            a0 = fma2(hd[i][12], v6.x, a0);
            a1 = fma2(hd[i][13], v6.y, a1);
            a0 = fma2(hd[i][14], v7.x, a0);
            a1 = fma2(hd[i][15], v7.y, a1);
            a0 = add2(a0, a1);               // (score_2p, score_2p+1)
            float slo, shi;
            unpack2(slo, shi, a0);
            if (slo > best[i]) { best[i] = slo; bidx[i] = 2 * p; }
            if (shi > best[i]) { best[i] = shi; bidx[i] = 2 * p + 1; }
        }
    }

#pragma unroll
    for (int i = 0; i < TPT; i++) {
        if (!valid[i]) continue;
        int gidx = kbase + bidx[i];
        unsigned ub = __float_as_uint(best[i]);
        ub = (ub & 0x80000000u) ? ~ub : (ub | 0x80000000u);  // sortable fp32
        u64 key = ((u64)ub << 32) | (unsigned)(0x7FFFFFFF - gidx);
        atomicMax(&g_keys[tok[i]], key);
    }
}

// ---------------------------------------------------------------------------
__global__ void rpq_finalize(float* __restrict__ out, int ntok, int total) {
    int t = blockIdx.x * blockDim.x + threadIdx.x;
    if (t < ntok)
        out[t] = (float)(0x7FFFFFFF - (int)(g_keys[t] & 0xFFFFFFFFull));
    else if (t < total)
        out[t] = 0.f;
}

// ---------------------------------------------------------------------------
extern "C" void kernel_launch(void* const* d_in, const int* in_sizes, int n_in,
                              void* d_out, int out_size) {
    // Bind by element count: hidden (largest), P (smallest), CB (remaining).
    int ih = 0, ip = 0;
    for (int i = 1; i < n_in; i++) {
        if (in_sizes[i] > in_sizes[ih]) ih = i;
        if (in_sizes[i] < in_sizes[ip]) ip = i;
    }
    int ic = 0;
    for (int i = 0; i < n_in; i++)
        if (i != ih && i != ip) ic = i;

    const float* hs = (const float*)d_in[ih];
    const float* P  = (const float*)d_in[ip];
    const float* CB = (const float*)d_in[ic];
    float* out = (float*)d_out;            // float32 labels (R6-proven)

    int ntok   = in_sizes[ih] / IN_DIM;    // 16000
    int kcodes = in_sizes[ic] / E;         // 8192

    rpq_proj_full<<<(ntok + PTHREADS - 1) / PTHREADS, PTHREADS>>>(hs, P, ntok);

    dim3 g2((ntok + TOKB - 1) / TOKB, kcodes / CHUNK);   // (63, 16)
    rpq_argmax<<<g2, THREADS>>>(CB, ntok, kcodes);

    rpq_finalize<<<(out_size + 255) / 256, 256>>>(out, ntok, out_size);
}